// round 1
// baseline (speedup 1.0000x reference)
#include <cuda_runtime.h>

// TransportKernel: two fused RBF-gram passes, never materializing the N x N grams.
//   pass1: A = Kfit @ Lam          (Kfit(i,j) = exp(-||xi-xj||^2 / 2))
//   pass2: loss = sum_ij Kmmd(i,j) * (diff_i . diff_j) + 0.01 * sum_i Lam_i . A_i
//          with diff = A - Y,  Kmmd(i,j) = exp(-||xi-xj||^2 / 8)

#define N 8192
#define D 16
#define TILE 256          // threads per CTA, one i-row per thread
#define ROWBLOCKS (N / TILE)   // 32
#define JSPLIT 16
#define JRANGE (N / JSPLIT)    // 512
#define SROW 20           // padded shared row stride (floats)

__device__ float g_A[N * D];   // Kfit @ Lam scratch
__device__ float g_sq[N];      // row squared norms of X

// ---------------------------------------------------------------------------
// prep: squared norms, zero A scratch, zero output scalar
// ---------------------------------------------------------------------------
__global__ void __launch_bounds__(TILE) prep_kernel(const float* __restrict__ X,
                                                    float* __restrict__ out) {
    int i = blockIdx.x * TILE + threadIdx.x;
    if (i == 0) out[0] = 0.0f;
    const float4* xp = (const float4*)(X + (size_t)i * D);
    float s = 0.0f;
#pragma unroll
    for (int k = 0; k < 4; k++) {
        float4 v = xp[k];
        s += v.x * v.x + v.y * v.y + v.z * v.z + v.w * v.w;
    }
    g_sq[i] = s;
    float4* ap = (float4*)(g_A + (size_t)i * D);
    float4 z = make_float4(0.f, 0.f, 0.f, 0.f);
#pragma unroll
    for (int k = 0; k < 4; k++) ap[k] = z;
}

// ---------------------------------------------------------------------------
// pass1: A[i][:] += sum_{j in split} exp(-d2(i,j)/2) * Lam[j][:]
// grid (ROWBLOCKS, JSPLIT)
// ---------------------------------------------------------------------------
__global__ void __launch_bounds__(TILE, 4) pass1_kernel(const float* __restrict__ X,
                                                        const float* __restrict__ Lam) {
    __shared__ float s_x[TILE][SROW];
    __shared__ float s_l[TILE][SROW];
    __shared__ float s_sq[TILE];

    const int i  = blockIdx.x * TILE + threadIdx.x;
    const int j0 = blockIdx.y * JRANGE;

    float mxi[D];   // -2 * X[i][:]
    float acc[D];
    const float4* xi4 = (const float4*)(X + (size_t)i * D);
#pragma unroll
    for (int k = 0; k < 4; k++) {
        float4 v = xi4[k];
        mxi[4 * k + 0] = -2.0f * v.x;
        mxi[4 * k + 1] = -2.0f * v.y;
        mxi[4 * k + 2] = -2.0f * v.z;
        mxi[4 * k + 3] = -2.0f * v.w;
    }
#pragma unroll
    for (int k = 0; k < D; k++) acc[k] = 0.0f;
    const float sqi = g_sq[i];

    for (int jt = j0; jt < j0 + JRANGE; jt += TILE) {
        const int j = jt + threadIdx.x;
        const float4* xj4 = (const float4*)(X + (size_t)j * D);
        const float4* lj4 = (const float4*)(Lam + (size_t)j * D);
#pragma unroll
        for (int k = 0; k < 4; k++) {
            *(float4*)&s_x[threadIdx.x][4 * k] = xj4[k];
            *(float4*)&s_l[threadIdx.x][4 * k] = lj4[k];
        }
        s_sq[threadIdx.x] = g_sq[j];
        __syncthreads();

#pragma unroll 1
        for (int jj = 0; jj < TILE; jj++) {
            const float* xs = s_x[jj];
            const float* ls = s_l[jj];
            float d0 = sqi + s_sq[jj];
            float d1 = 0.0f;
#pragma unroll
            for (int k = 0; k < D; k += 2) {
                d0 = fmaf(mxi[k],     xs[k],     d0);
                d1 = fmaf(mxi[k + 1], xs[k + 1], d1);
            }
            const float kk = __expf((d0 + d1) * -0.5f);
#pragma unroll
            for (int k = 0; k < D; k++) acc[k] = fmaf(kk, ls[k], acc[k]);
        }
        __syncthreads();
    }

#pragma unroll
    for (int k = 0; k < D; k++) atomicAdd(&g_A[(size_t)i * D + k], acc[k]);
}

// ---------------------------------------------------------------------------
// pass2: out += sum_{i, j in split} exp(-d2(i,j)/8) * (diff_i . diff_j)
//        + (split 0 only) 0.01 * Lam_i . A_i
// grid (ROWBLOCKS, JSPLIT)
// ---------------------------------------------------------------------------
__global__ void __launch_bounds__(TILE, 4) pass2_kernel(const float* __restrict__ X,
                                                        const float* __restrict__ Y,
                                                        const float* __restrict__ Lam,
                                                        float* __restrict__ out) {
    __shared__ float s_x[TILE][SROW];
    __shared__ float s_df[TILE][SROW];
    __shared__ float s_sq[TILE];
    __shared__ float s_red[TILE / 32];

    const int i  = blockIdx.x * TILE + threadIdx.x;
    const int j0 = blockIdx.y * JRANGE;

    float mxi[D];   // -2 * X[i][:]
    float di[D];    // diff_i = A_i - Y_i
    const float4* xi4 = (const float4*)(X + (size_t)i * D);
    const float4* ai4 = (const float4*)(g_A + (size_t)i * D);
    const float4* yi4 = (const float4*)(Y + (size_t)i * D);
#pragma unroll
    for (int k = 0; k < 4; k++) {
        float4 v = xi4[k];
        mxi[4 * k + 0] = -2.0f * v.x;
        mxi[4 * k + 1] = -2.0f * v.y;
        mxi[4 * k + 2] = -2.0f * v.z;
        mxi[4 * k + 3] = -2.0f * v.w;
        float4 a = ai4[k];
        float4 y = yi4[k];
        di[4 * k + 0] = a.x - y.x;
        di[4 * k + 1] = a.y - y.y;
        di[4 * k + 2] = a.z - y.z;
        di[4 * k + 3] = a.w - y.w;
    }
    const float sqi = g_sq[i];

    float part = 0.0f;
    if (blockIdx.y == 0) {  // regularizer term, counted once per row
        const float4* li4 = (const float4*)(Lam + (size_t)i * D);
        float r = 0.0f;
#pragma unroll
        for (int k = 0; k < 4; k++) {
            float4 l = li4[k];
            float4 a = ai4[k];
            r += l.x * a.x + l.y * a.y + l.z * a.z + l.w * a.w;
        }
        part = 0.01f * r;
    }

    for (int jt = j0; jt < j0 + JRANGE; jt += TILE) {
        const int j = jt + threadIdx.x;
        const float4* xj4 = (const float4*)(X + (size_t)j * D);
        const float4* aj4 = (const float4*)(g_A + (size_t)j * D);
        const float4* yj4 = (const float4*)(Y + (size_t)j * D);
#pragma unroll
        for (int k = 0; k < 4; k++) {
            *(float4*)&s_x[threadIdx.x][4 * k] = xj4[k];
            float4 a = aj4[k];
            float4 y = yj4[k];
            s_df[threadIdx.x][4 * k + 0] = a.x - y.x;
            s_df[threadIdx.x][4 * k + 1] = a.y - y.y;
            s_df[threadIdx.x][4 * k + 2] = a.z - y.z;
            s_df[threadIdx.x][4 * k + 3] = a.w - y.w;
        }
        s_sq[threadIdx.x] = g_sq[j];
        __syncthreads();

#pragma unroll 1
        for (int jj = 0; jj < TILE; jj++) {
            const float* xs  = s_x[jj];
            const float* dfs = s_df[jj];
            float d0 = sqi + s_sq[jj];
            float d1 = 0.0f;
            float t0 = 0.0f, t1 = 0.0f;
#pragma unroll
            for (int k = 0; k < D; k += 2) {
                d0 = fmaf(mxi[k],     xs[k],     d0);
                d1 = fmaf(mxi[k + 1], xs[k + 1], d1);
                t0 = fmaf(di[k],      dfs[k],    t0);
                t1 = fmaf(di[k + 1],  dfs[k + 1], t1);
            }
            const float kk = __expf((d0 + d1) * -0.125f);
            part = fmaf(kk, t0 + t1, part);
        }
        __syncthreads();
    }

    // block reduction -> one atomic per CTA (keeps fp32 rounding error low)
#pragma unroll
    for (int o = 16; o > 0; o >>= 1) part += __shfl_xor_sync(0xffffffffu, part, o);
    const int lane = threadIdx.x & 31;
    const int wid  = threadIdx.x >> 5;
    if (lane == 0) s_red[wid] = part;
    __syncthreads();
    if (threadIdx.x == 0) {
        float t = 0.0f;
#pragma unroll
        for (int w = 0; w < TILE / 32; w++) t += s_red[w];
        atomicAdd(out, t);
    }
}

// ---------------------------------------------------------------------------
extern "C" void kernel_launch(void* const* d_in, const int* in_sizes, int n_in,
                              void* d_out, int out_size) {
    const float* X   = (const float*)d_in[0];
    const float* Y   = (const float*)d_in[1];
    const float* Lam = (const float*)d_in[2];
    float* out = (float*)d_out;

    prep_kernel<<<ROWBLOCKS, TILE>>>(X, out);

    dim3 grid(ROWBLOCKS, JSPLIT);
    pass1_kernel<<<grid, TILE>>>(X, Lam);
    pass2_kernel<<<grid, TILE>>>(X, Y, Lam, out);
}

// round 2
// speedup vs baseline: 1.4384x; 1.4384x over previous
#include <cuda_runtime.h>

// TransportKernel: two fused RBF-gram passes, never materializing the N x N grams.
//   pass1: A = Kfit @ Lam                    Kfit(i,j) = exp(-||xi-xj||^2 / 2)
//   pass2: loss = sum_ij Kmmd(i,j)*(d_i.d_j) + 0.01 * sum_i Lam_i . A_i
//          d = A - Y,  Kmmd(i,j) = exp(-||xi-xj||^2 / 8)
// R1: packed f32x2 FMA (SASS FFMA2) in both inner loops; block-triangular
//     symmetry in pass 2 (weight-2 off-diagonal tiles).

#define N 8192
#define D 16
#define TILE 256
#define ROWBLOCKS (N / TILE)     // 32
#define JSPLIT 16
#define JRANGE (N / JSPLIT)      // 512 (pass 1)
#define SROW 20                  // padded shared row stride in floats (80B, 16B-mult)

typedef unsigned long long u64;

#define LOG2E 1.4426950408889634f

__device__ float g_A[N * D];     // Kfit @ Lam scratch
__device__ float g_sq[N];        // row squared norms of X

// ---- packed f32x2 helpers --------------------------------------------------
__device__ __forceinline__ u64 fma2(u64 a, u64 b, u64 c) {
    u64 d;
    asm("fma.rn.f32x2 %0, %1, %2, %3;" : "=l"(d) : "l"(a), "l"(b), "l"(c));
    return d;
}
__device__ __forceinline__ u64 add2(u64 a, u64 b) {
    u64 d;
    asm("add.rn.f32x2 %0, %1, %2;" : "=l"(d) : "l"(a), "l"(b));
    return d;
}
__device__ __forceinline__ u64 pack2(float lo, float hi) {
    u64 r;
    asm("mov.b64 %0, {%1, %2};" : "=l"(r) : "f"(lo), "f"(hi));
    return r;
}
__device__ __forceinline__ float2 unpack2(u64 v) {
    float2 r;
    asm("mov.b64 {%0, %1}, %2;" : "=f"(r.x), "=f"(r.y) : "l"(v));
    return r;
}
__device__ __forceinline__ float ex2a(float x) {
    float y;
    asm("ex2.approx.f32 %0, %1;" : "=f"(y) : "f"(x));
    return y;
}

// ---------------------------------------------------------------------------
// prep: squared norms, zero A scratch, zero output scalar
// ---------------------------------------------------------------------------
__global__ void __launch_bounds__(TILE) prep_kernel(const float* __restrict__ X,
                                                    float* __restrict__ out) {
    int i = blockIdx.x * TILE + threadIdx.x;
    if (i == 0) out[0] = 0.0f;
    const float4* xp = (const float4*)(X + (size_t)i * D);
    float s = 0.0f;
#pragma unroll
    for (int k = 0; k < 4; k++) {
        float4 v = xp[k];
        s += v.x * v.x + v.y * v.y + v.z * v.z + v.w * v.w;
    }
    g_sq[i] = s;
    float4* ap = (float4*)(g_A + (size_t)i * D);
    float4 z = make_float4(0.f, 0.f, 0.f, 0.f);
#pragma unroll
    for (int k = 0; k < 4; k++) ap[k] = z;
}

// ---------------------------------------------------------------------------
// pass1: A[i][:] += sum_{j in split} exp(-d2(i,j)/2) * Lam[j][:]
// grid (ROWBLOCKS, JSPLIT)
// ---------------------------------------------------------------------------
__global__ void __launch_bounds__(TILE, 4) pass1_kernel(const float* __restrict__ X,
                                                        const float* __restrict__ Lam) {
    __shared__ float s_x[TILE][SROW];
    __shared__ float s_l[TILE][SROW];
    __shared__ float s_sq[TILE];

    const int i  = blockIdx.x * TILE + threadIdx.x;
    const int j0 = blockIdx.y * JRANGE;
    const float cexp = -0.5f * LOG2E;

    u64 mx[8];   // packed -2*X[i][:]
    u64 acc[8];
    const float4* xi4 = (const float4*)(X + (size_t)i * D);
#pragma unroll
    for (int k = 0; k < 4; k++) {
        float4 v = xi4[k];
        mx[2 * k + 0] = pack2(-2.0f * v.x, -2.0f * v.y);
        mx[2 * k + 1] = pack2(-2.0f * v.z, -2.0f * v.w);
    }
#pragma unroll
    for (int k = 0; k < 8; k++) acc[k] = 0ull;
    const float argbase = cexp * g_sq[i];   // cexp*(sqi + sqj + dot) folded

    for (int jt = j0; jt < j0 + JRANGE; jt += TILE) {
        const int j = jt + threadIdx.x;
        const float4* xj4 = (const float4*)(X + (size_t)j * D);
        const float4* lj4 = (const float4*)(Lam + (size_t)j * D);
#pragma unroll
        for (int k = 0; k < 4; k++) {
            *(float4*)&s_x[threadIdx.x][4 * k] = xj4[k];
            *(float4*)&s_l[threadIdx.x][4 * k] = lj4[k];
        }
        s_sq[threadIdx.x] = g_sq[j];
        __syncthreads();

#pragma unroll 1
        for (int jj = 0; jj < TILE; jj++) {
            const ulonglong2* xs = (const ulonglong2*)s_x[jj];
            const ulonglong2* ls = (const ulonglong2*)s_l[jj];
            ulonglong2 x0 = xs[0], x1 = xs[1], x2 = xs[2], x3 = xs[3];
            u64 d0 = fma2(mx[0], x0.x, 0ull);
            u64 d1 = fma2(mx[1], x0.y, 0ull);
            d0 = fma2(mx[2], x1.x, d0);
            d1 = fma2(mx[3], x1.y, d1);
            d0 = fma2(mx[4], x2.x, d0);
            d1 = fma2(mx[5], x2.y, d1);
            d0 = fma2(mx[6], x3.x, d0);
            d1 = fma2(mx[7], x3.y, d1);
            float2 dp = unpack2(add2(d0, d1));
            const float arg = fmaf(cexp, (dp.x + dp.y) + s_sq[jj], argbase);
            const float kk = ex2a(arg);
            const u64 kk2 = pack2(kk, kk);
            ulonglong2 l0 = ls[0], l1 = ls[1], l2 = ls[2], l3 = ls[3];
            acc[0] = fma2(kk2, l0.x, acc[0]);
            acc[1] = fma2(kk2, l0.y, acc[1]);
            acc[2] = fma2(kk2, l1.x, acc[2]);
            acc[3] = fma2(kk2, l1.y, acc[3]);
            acc[4] = fma2(kk2, l2.x, acc[4]);
            acc[5] = fma2(kk2, l2.y, acc[5]);
            acc[6] = fma2(kk2, l3.x, acc[6]);
            acc[7] = fma2(kk2, l3.y, acc[7]);
        }
        __syncthreads();
    }

#pragma unroll
    for (int k = 0; k < 8; k++) {
        float2 f = unpack2(acc[k]);
        atomicAdd(&g_A[(size_t)i * D + 2 * k + 0], f.x);
        atomicAdd(&g_A[(size_t)i * D + 2 * k + 1], f.y);
    }
}

// ---------------------------------------------------------------------------
// pass2: out += w * sum_{i in bi, j in bj} exp(-d2/8) * (d_i . d_j)
//        grid (32, 32), only bj >= bi active; w = 1 on diagonal, 2 above.
//        + (bi==bj) regularizer 0.01 * Lam_i . A_i
// ---------------------------------------------------------------------------
__global__ void __launch_bounds__(TILE, 4) pass2_kernel(const float* __restrict__ X,
                                                        const float* __restrict__ Y,
                                                        const float* __restrict__ Lam,
                                                        float* __restrict__ out) {
    const int bi = blockIdx.x;
    const int bj = blockIdx.y;
    if (bj < bi) return;   // triangular: symmetric summand

    __shared__ float s_x[TILE][SROW];
    __shared__ float s_df[TILE][SROW];
    __shared__ float s_sq[TILE];
    __shared__ float s_red[TILE / 32];

    const int i = bi * TILE + threadIdx.x;
    const int j = bj * TILE + threadIdx.x;
    const float cexp = -0.125f * LOG2E;

    u64 mx[8];   // packed -2*X[i][:]
    u64 di[8];   // packed diff_i = A_i - Y_i
    const float4* xi4 = (const float4*)(X + (size_t)i * D);
    const float4* ai4 = (const float4*)(g_A + (size_t)i * D);
    const float4* yi4 = (const float4*)(Y + (size_t)i * D);
#pragma unroll
    for (int k = 0; k < 4; k++) {
        float4 v = xi4[k];
        mx[2 * k + 0] = pack2(-2.0f * v.x, -2.0f * v.y);
        mx[2 * k + 1] = pack2(-2.0f * v.z, -2.0f * v.w);
        float4 a = ai4[k];
        float4 y = yi4[k];
        di[2 * k + 0] = pack2(a.x - y.x, a.y - y.y);
        di[2 * k + 1] = pack2(a.z - y.z, a.w - y.w);
    }
    const float argbase = cexp * g_sq[i];

    // load j tile: X row + diff row + sq
    {
        const float4* xj4 = (const float4*)(X + (size_t)j * D);
        const float4* aj4 = (const float4*)(g_A + (size_t)j * D);
        const float4* yj4 = (const float4*)(Y + (size_t)j * D);
#pragma unroll
        for (int k = 0; k < 4; k++) {
            *(float4*)&s_x[threadIdx.x][4 * k] = xj4[k];
            float4 a = aj4[k];
            float4 y = yj4[k];
            s_df[threadIdx.x][4 * k + 0] = a.x - y.x;
            s_df[threadIdx.x][4 * k + 1] = a.y - y.y;
            s_df[threadIdx.x][4 * k + 2] = a.z - y.z;
            s_df[threadIdx.x][4 * k + 3] = a.w - y.w;
        }
        s_sq[threadIdx.x] = g_sq[j];
    }
    __syncthreads();

    float part = 0.0f;
#pragma unroll 1
    for (int jj = 0; jj < TILE; jj++) {
        const ulonglong2* xs  = (const ulonglong2*)s_x[jj];
        const ulonglong2* dfs = (const ulonglong2*)s_df[jj];
        ulonglong2 x0 = xs[0], x1 = xs[1], x2 = xs[2], x3 = xs[3];
        u64 d0 = fma2(mx[0], x0.x, 0ull);
        u64 d1 = fma2(mx[1], x0.y, 0ull);
        d0 = fma2(mx[2], x1.x, d0);
        d1 = fma2(mx[3], x1.y, d1);
        d0 = fma2(mx[4], x2.x, d0);
        d1 = fma2(mx[5], x2.y, d1);
        d0 = fma2(mx[6], x3.x, d0);
        d1 = fma2(mx[7], x3.y, d1);
        ulonglong2 f0 = dfs[0], f1 = dfs[1], f2 = dfs[2], f3 = dfs[3];
        u64 t0 = fma2(di[0], f0.x, 0ull);
        u64 t1 = fma2(di[1], f0.y, 0ull);
        t0 = fma2(di[2], f1.x, t0);
        t1 = fma2(di[3], f1.y, t1);
        t0 = fma2(di[4], f2.x, t0);
        t1 = fma2(di[5], f2.y, t1);
        t0 = fma2(di[6], f3.x, t0);
        t1 = fma2(di[7], f3.y, t1);
        float2 dp = unpack2(add2(d0, d1));
        const float arg = fmaf(cexp, (dp.x + dp.y) + s_sq[jj], argbase);
        const float kk = ex2a(arg);
        float2 tp = unpack2(add2(t0, t1));
        part = fmaf(kk, tp.x + tp.y, part);
    }

    if (bj != bi) part *= 2.0f;      // off-diagonal tile counted twice (exact)
    else {                            // diagonal tile: add regularizer once per row
        const float4* li4 = (const float4*)(Lam + (size_t)i * D);
        float r = 0.0f;
#pragma unroll
        for (int k = 0; k < 4; k++) {
            float4 l = li4[k];
            float4 a = ai4[k];
            r += l.x * a.x + l.y * a.y + l.z * a.z + l.w * a.w;
        }
        part = fmaf(0.01f, r, part);
    }

    // block reduction -> one atomic per CTA
#pragma unroll
    for (int o = 16; o > 0; o >>= 1) part += __shfl_xor_sync(0xffffffffu, part, o);
    const int lane = threadIdx.x & 31;
    const int wid  = threadIdx.x >> 5;
    if (lane == 0) s_red[wid] = part;
    __syncthreads();
    if (threadIdx.x == 0) {
        float t = 0.0f;
#pragma unroll
        for (int w = 0; w < TILE / 32; w++) t += s_red[w];
        atomicAdd(out, t);
    }
}

// ---------------------------------------------------------------------------
extern "C" void kernel_launch(void* const* d_in, const int* in_sizes, int n_in,
                              void* d_out, int out_size) {
    const float* X   = (const float*)d_in[0];
    const float* Y   = (const float*)d_in[1];
    const float* Lam = (const float*)d_in[2];
    float* out = (float*)d_out;

    prep_kernel<<<ROWBLOCKS, TILE>>>(X, out);

    dim3 grid1(ROWBLOCKS, JSPLIT);
    pass1_kernel<<<grid1, TILE>>>(X, Lam);

    dim3 grid2(ROWBLOCKS, ROWBLOCKS);
    pass2_kernel<<<grid2, TILE>>>(X, Y, Lam, out);
}

// round 3
// speedup vs baseline: 1.7086x; 1.1879x over previous
#include <cuda_runtime.h>

// TransportKernel: two fused RBF-gram passes, never materializing the N x N grams.
//   pass1: A = Kfit @ Lam                    Kfit(i,j) = exp(-||xi-xj||^2 / 2)
//   pass2: loss = sum_ij Kmmd(i,j)*(d_i.d_j) + 0.01 * sum_i Lam_i . A_i
//          d = A - Y,  Kmmd(i,j) = exp(-||xi-xj||^2 / 8)
// R1: packed f32x2 FMA (FFMA2); block-triangular pass 2.
// R2: i-blocking x2 (each thread owns rows i and i+128) -> shared-tile LDS and
//     issue overhead amortized over 2x pairs; FMA pipe becomes sole binding pipe.

#define N 8192
#define D 16
#define TILE 128                  // threads per CTA
#define IBLK 2
#define ROWS_CTA (TILE * IBLK)    // 256 i-rows per CTA
#define NBLK (N / ROWS_CTA)       // 32
#define JSPLIT 16
#define JRANGE (N / JSPLIT)       // 512
#define JTILE 128                 // j-rows per shared tile
#define SROW 20                   // padded shared row stride (floats); slot 16 = cexp*sq

typedef unsigned long long u64;

#define LOG2E 1.4426950408889634f

__device__ float g_A[N * D];      // Kfit @ Lam scratch
__device__ float g_sq[N];         // row squared norms of X

// ---- packed f32x2 helpers --------------------------------------------------
__device__ __forceinline__ u64 fma2(u64 a, u64 b, u64 c) {
    u64 d;
    asm("fma.rn.f32x2 %0, %1, %2, %3;" : "=l"(d) : "l"(a), "l"(b), "l"(c));
    return d;
}
__device__ __forceinline__ u64 add2(u64 a, u64 b) {
    u64 d;
    asm("add.rn.f32x2 %0, %1, %2;" : "=l"(d) : "l"(a), "l"(b));
    return d;
}
__device__ __forceinline__ u64 pack2(float lo, float hi) {
    u64 r;
    asm("mov.b64 %0, {%1, %2};" : "=l"(r) : "f"(lo), "f"(hi));
    return r;
}
__device__ __forceinline__ float2 unpack2(u64 v) {
    float2 r;
    asm("mov.b64 {%0, %1}, %2;" : "=f"(r.x), "=f"(r.y) : "l"(v));
    return r;
}
__device__ __forceinline__ float ex2a(float x) {
    float y;
    asm("ex2.approx.f32 %0, %1;" : "=f"(y) : "f"(x));
    return y;
}

// ---------------------------------------------------------------------------
// prep: squared norms, zero A scratch, zero output scalar
// ---------------------------------------------------------------------------
__global__ void __launch_bounds__(256) prep_kernel(const float* __restrict__ X,
                                                   float* __restrict__ out) {
    int i = blockIdx.x * 256 + threadIdx.x;
    if (i == 0) out[0] = 0.0f;
    const float4* xp = (const float4*)(X + (size_t)i * D);
    float s = 0.0f;
#pragma unroll
    for (int k = 0; k < 4; k++) {
        float4 v = xp[k];
        s += v.x * v.x + v.y * v.y + v.z * v.z + v.w * v.w;
    }
    g_sq[i] = s;
    float4* ap = (float4*)(g_A + (size_t)i * D);
    float4 z = make_float4(0.f, 0.f, 0.f, 0.f);
#pragma unroll
    for (int k = 0; k < 4; k++) ap[k] = z;
}

// ---------------------------------------------------------------------------
// pass1: A[i][:] += sum_{j in split} exp(-d2(i,j)/2) * Lam[j][:]
// grid (NBLK, JSPLIT); thread owns rows i0 = b*256+t and i1 = i0+128
// ---------------------------------------------------------------------------
__global__ void __launch_bounds__(TILE, 4) pass1_kernel(const float* __restrict__ X,
                                                        const float* __restrict__ Lam) {
    __shared__ float s_x[JTILE][SROW];
    __shared__ float s_l[JTILE][SROW];

    const int t  = threadIdx.x;
    const int i0 = blockIdx.x * ROWS_CTA + t;
    const int i1 = i0 + TILE;
    const int j0 = blockIdx.y * JRANGE;
    const float cexp = -0.5f * LOG2E;

    u64 mx0[8], mx1[8];             // packed -2*X[i][:]
    u64 acc0[8], acc1[8];
    {
        const float4* p0 = (const float4*)(X + (size_t)i0 * D);
        const float4* p1 = (const float4*)(X + (size_t)i1 * D);
#pragma unroll
        for (int k = 0; k < 4; k++) {
            float4 a = p0[k];
            mx0[2 * k + 0] = pack2(-2.0f * a.x, -2.0f * a.y);
            mx0[2 * k + 1] = pack2(-2.0f * a.z, -2.0f * a.w);
            float4 b = p1[k];
            mx1[2 * k + 0] = pack2(-2.0f * b.x, -2.0f * b.y);
            mx1[2 * k + 1] = pack2(-2.0f * b.z, -2.0f * b.w);
        }
    }
#pragma unroll
    for (int k = 0; k < 8; k++) { acc0[k] = 0ull; acc1[k] = 0ull; }
    const float base0 = cexp * g_sq[i0];
    const float base1 = cexp * g_sq[i1];

    for (int jt = j0; jt < j0 + JRANGE; jt += JTILE) {
        const int j = jt + t;
        const float4* xj4 = (const float4*)(X + (size_t)j * D);
        const float4* lj4 = (const float4*)(Lam + (size_t)j * D);
#pragma unroll
        for (int k = 0; k < 4; k++) {
            *(float4*)&s_x[t][4 * k] = xj4[k];
            *(float4*)&s_l[t][4 * k] = lj4[k];
        }
        s_x[t][16] = cexp * g_sq[j];
        __syncthreads();

#pragma unroll 1
        for (int jj = 0; jj < JTILE; jj++) {
            const ulonglong2* xs = (const ulonglong2*)s_x[jj];
            const ulonglong2* ls = (const ulonglong2*)s_l[jj];
            ulonglong2 x0 = xs[0], x1 = xs[1], x2 = xs[2], x3 = xs[3];
            const float sqc = s_x[jj][16];

            u64 a0 = fma2(mx0[0], x0.x, 0ull);
            u64 a1 = fma2(mx0[1], x0.y, 0ull);
            u64 b0 = fma2(mx1[0], x0.x, 0ull);
            u64 b1 = fma2(mx1[1], x0.y, 0ull);
            a0 = fma2(mx0[2], x1.x, a0);  a1 = fma2(mx0[3], x1.y, a1);
            b0 = fma2(mx1[2], x1.x, b0);  b1 = fma2(mx1[3], x1.y, b1);
            a0 = fma2(mx0[4], x2.x, a0);  a1 = fma2(mx0[5], x2.y, a1);
            b0 = fma2(mx1[4], x2.x, b0);  b1 = fma2(mx1[5], x2.y, b1);
            a0 = fma2(mx0[6], x3.x, a0);  a1 = fma2(mx0[7], x3.y, a1);
            b0 = fma2(mx1[6], x3.x, b0);  b1 = fma2(mx1[7], x3.y, b1);

            float2 da = unpack2(add2(a0, a1));
            float2 db = unpack2(add2(b0, b1));
            const float kk0 = ex2a(fmaf(cexp, da.x + da.y, base0 + sqc));
            const float kk1 = ex2a(fmaf(cexp, db.x + db.y, base1 + sqc));
            const u64 kp0 = pack2(kk0, kk0);
            const u64 kp1 = pack2(kk1, kk1);

            ulonglong2 l0 = ls[0], l1 = ls[1], l2 = ls[2], l3 = ls[3];
            acc0[0] = fma2(kp0, l0.x, acc0[0]);  acc1[0] = fma2(kp1, l0.x, acc1[0]);
            acc0[1] = fma2(kp0, l0.y, acc0[1]);  acc1[1] = fma2(kp1, l0.y, acc1[1]);
            acc0[2] = fma2(kp0, l1.x, acc0[2]);  acc1[2] = fma2(kp1, l1.x, acc1[2]);
            acc0[3] = fma2(kp0, l1.y, acc0[3]);  acc1[3] = fma2(kp1, l1.y, acc1[3]);
            acc0[4] = fma2(kp0, l2.x, acc0[4]);  acc1[4] = fma2(kp1, l2.x, acc1[4]);
            acc0[5] = fma2(kp0, l2.y, acc0[5]);  acc1[5] = fma2(kp1, l2.y, acc1[5]);
            acc0[6] = fma2(kp0, l3.x, acc0[6]);  acc1[6] = fma2(kp1, l3.x, acc1[6]);
            acc0[7] = fma2(kp0, l3.y, acc0[7]);  acc1[7] = fma2(kp1, l3.y, acc1[7]);
        }
        __syncthreads();
    }

#pragma unroll
    for (int k = 0; k < 8; k++) {
        float2 f0 = unpack2(acc0[k]);
        atomicAdd(&g_A[(size_t)i0 * D + 2 * k + 0], f0.x);
        atomicAdd(&g_A[(size_t)i0 * D + 2 * k + 1], f0.y);
        float2 f1 = unpack2(acc1[k]);
        atomicAdd(&g_A[(size_t)i1 * D + 2 * k + 0], f1.x);
        atomicAdd(&g_A[(size_t)i1 * D + 2 * k + 1], f1.y);
    }
}

// ---------------------------------------------------------------------------
// pass2: out += w * sum_{i in bi, j in bj} exp(-d2/8) * (d_i . d_j)
//        grid (NBLK, NBLK), only bj >= bi active; w = 1 diag, 2 above.
//        + (bi==bj) regularizer 0.01 * Lam_i . A_i
// ---------------------------------------------------------------------------
__global__ void __launch_bounds__(TILE, 4) pass2_kernel(const float* __restrict__ X,
                                                        const float* __restrict__ Y,
                                                        const float* __restrict__ Lam,
                                                        float* __restrict__ out) {
    const int bi = blockIdx.x;
    const int bj = blockIdx.y;
    if (bj < bi) return;

    __shared__ float s_x[JTILE][SROW];
    __shared__ float s_df[JTILE][SROW];
    __shared__ float s_red[TILE / 32];

    const int t  = threadIdx.x;
    const int i0 = bi * ROWS_CTA + t;
    const int i1 = i0 + TILE;
    const float cexp = -0.125f * LOG2E;

    u64 mx0[8], mx1[8];            // packed -2*X[i][:]
    u64 di0[8], di1[8];            // packed diff_i = A_i - Y_i
    {
        const float4* p0 = (const float4*)(X + (size_t)i0 * D);
        const float4* p1 = (const float4*)(X + (size_t)i1 * D);
        const float4* a0p = (const float4*)(g_A + (size_t)i0 * D);
        const float4* a1p = (const float4*)(g_A + (size_t)i1 * D);
        const float4* y0p = (const float4*)(Y + (size_t)i0 * D);
        const float4* y1p = (const float4*)(Y + (size_t)i1 * D);
#pragma unroll
        for (int k = 0; k < 4; k++) {
            float4 v = p0[k];
            mx0[2 * k + 0] = pack2(-2.0f * v.x, -2.0f * v.y);
            mx0[2 * k + 1] = pack2(-2.0f * v.z, -2.0f * v.w);
            float4 w = p1[k];
            mx1[2 * k + 0] = pack2(-2.0f * w.x, -2.0f * w.y);
            mx1[2 * k + 1] = pack2(-2.0f * w.z, -2.0f * w.w);
            float4 a = a0p[k], y = y0p[k];
            di0[2 * k + 0] = pack2(a.x - y.x, a.y - y.y);
            di0[2 * k + 1] = pack2(a.z - y.z, a.w - y.w);
            float4 c = a1p[k], z = y1p[k];
            di1[2 * k + 0] = pack2(c.x - z.x, c.y - z.y);
            di1[2 * k + 1] = pack2(c.z - z.z, c.w - z.w);
        }
    }
    const float base0 = cexp * g_sq[i0];
    const float base1 = cexp * g_sq[i1];

    float part0 = 0.0f, part1 = 0.0f;

    // two j-tiles of 128 covering this 256-row j block
    const int jb = bj * ROWS_CTA;
#pragma unroll 1
    for (int half = 0; half < IBLK; half++) {
        const int j = jb + half * JTILE + t;
        {
            const float4* xj4 = (const float4*)(X + (size_t)j * D);
            const float4* aj4 = (const float4*)(g_A + (size_t)j * D);
            const float4* yj4 = (const float4*)(Y + (size_t)j * D);
#pragma unroll
            for (int k = 0; k < 4; k++) {
                *(float4*)&s_x[t][4 * k] = xj4[k];
                float4 a = aj4[k];
                float4 y = yj4[k];
                s_df[t][4 * k + 0] = a.x - y.x;
                s_df[t][4 * k + 1] = a.y - y.y;
                s_df[t][4 * k + 2] = a.z - y.z;
                s_df[t][4 * k + 3] = a.w - y.w;
            }
            s_x[t][16] = cexp * g_sq[j];
        }
        __syncthreads();

#pragma unroll 1
        for (int jj = 0; jj < JTILE; jj++) {
            const ulonglong2* xs  = (const ulonglong2*)s_x[jj];
            const ulonglong2* dfs = (const ulonglong2*)s_df[jj];
            ulonglong2 x0 = xs[0], x1 = xs[1], x2 = xs[2], x3 = xs[3];
            const float sqc = s_x[jj][16];

            u64 a0 = fma2(mx0[0], x0.x, 0ull);
            u64 a1 = fma2(mx0[1], x0.y, 0ull);
            u64 b0 = fma2(mx1[0], x0.x, 0ull);
            u64 b1 = fma2(mx1[1], x0.y, 0ull);
            a0 = fma2(mx0[2], x1.x, a0);  a1 = fma2(mx0[3], x1.y, a1);
            b0 = fma2(mx1[2], x1.x, b0);  b1 = fma2(mx1[3], x1.y, b1);
            a0 = fma2(mx0[4], x2.x, a0);  a1 = fma2(mx0[5], x2.y, a1);
            b0 = fma2(mx1[4], x2.x, b0);  b1 = fma2(mx1[5], x2.y, b1);
            a0 = fma2(mx0[6], x3.x, a0);  a1 = fma2(mx0[7], x3.y, a1);
            b0 = fma2(mx1[6], x3.x, b0);  b1 = fma2(mx1[7], x3.y, b1);

            ulonglong2 f0 = dfs[0], f1 = dfs[1], f2 = dfs[2], f3 = dfs[3];
            u64 t0 = fma2(di0[0], f0.x, 0ull);
            u64 t1 = fma2(di0[1], f0.y, 0ull);
            u64 u0 = fma2(di1[0], f0.x, 0ull);
            u64 u1 = fma2(di1[1], f0.y, 0ull);
            t0 = fma2(di0[2], f1.x, t0);  t1 = fma2(di0[3], f1.y, t1);
            u0 = fma2(di1[2], f1.x, u0);  u1 = fma2(di1[3], f1.y, u1);
            t0 = fma2(di0[4], f2.x, t0);  t1 = fma2(di0[5], f2.y, t1);
            u0 = fma2(di1[4], f2.x, u0);  u1 = fma2(di1[5], f2.y, u1);
            t0 = fma2(di0[6], f3.x, t0);  t1 = fma2(di0[7], f3.y, t1);
            u0 = fma2(di1[6], f3.x, u0);  u1 = fma2(di1[7], f3.y, u1);

            float2 da = unpack2(add2(a0, a1));
            float2 db = unpack2(add2(b0, b1));
            const float kk0 = ex2a(fmaf(cexp, da.x + da.y, base0 + sqc));
            const float kk1 = ex2a(fmaf(cexp, db.x + db.y, base1 + sqc));
            float2 tp = unpack2(add2(t0, t1));
            float2 up = unpack2(add2(u0, u1));
            part0 = fmaf(kk0, tp.x + tp.y, part0);
            part1 = fmaf(kk1, up.x + up.y, part1);
        }
        __syncthreads();
    }

    float part = part0 + part1;
    if (bj != bi) part *= 2.0f;   // off-diagonal tile counted twice (exact)
    else {                         // diagonal tile: regularizer, once per row
        const float4* l0p = (const float4*)(Lam + (size_t)i0 * D);
        const float4* l1p = (const float4*)(Lam + (size_t)i1 * D);
        const float4* a0p = (const float4*)(g_A + (size_t)i0 * D);
        const float4* a1p = (const float4*)(g_A + (size_t)i1 * D);
        float r = 0.0f;
#pragma unroll
        for (int k = 0; k < 4; k++) {
            float4 l = l0p[k], a = a0p[k];
            r += l.x * a.x + l.y * a.y + l.z * a.z + l.w * a.w;
            float4 m = l1p[k], b = a1p[k];
            r += m.x * b.x + m.y * b.y + m.z * b.z + m.w * b.w;
        }
        part = fmaf(0.01f, r, part);
    }

    // block reduction -> one atomic per CTA
#pragma unroll
    for (int o = 16; o > 0; o >>= 1) part += __shfl_xor_sync(0xffffffffu, part, o);
    const int lane = threadIdx.x & 31;
    const int wid  = threadIdx.x >> 5;
    if (lane == 0) s_red[wid] = part;
    __syncthreads();
    if (threadIdx.x == 0) {
        float tsum = 0.0f;
#pragma unroll
        for (int w = 0; w < TILE / 32; w++) tsum += s_red[w];
        atomicAdd(out, tsum);
    }
}

// ---------------------------------------------------------------------------
extern "C" void kernel_launch(void* const* d_in, const int* in_sizes, int n_in,
                              void* d_out, int out_size) {
    const float* X   = (const float*)d_in[0];
    const float* Y   = (const float*)d_in[1];
    const float* Lam = (const float*)d_in[2];
    float* out = (float*)d_out;

    prep_kernel<<<N / 256, 256>>>(X, out);

    dim3 grid1(NBLK, JSPLIT);
    pass1_kernel<<<grid1, TILE>>>(X, Lam);

    dim3 grid2(NBLK, NBLK);
    pass2_kernel<<<grid2, TILE>>>(X, Y, Lam, out);
}

// round 12
// speedup vs baseline: 2.7230x; 1.5937x over previous
#include <cuda_runtime.h>
#include <cuda_bf16.h>
#include <cstdint>

// TransportKernel via warp-level mma.sync (HMMA bf16) — R9.
// R6 bug: host code passed __device__ globals (g_A/g_diff/g_W) as kernel args;
// on GB300 ATS makes the host shadow addresses dereferenceable, so rbf_mv
// silently wrote HOST memory and the device arrays stayed zero -> out == 0.
// Fix: device-side mode selector (as in R3). Datapath unchanged.
//
// Both RBF passes are one primitive:  W = K_gamma(X) @ V
//   pass1: V = Lam   -> A    (gamma = -log2(e)/2)
//   pass2: V = A - Y -> W    (gamma = -log2(e)/8)
// loss = sum(diff .* W) + 0.01 * sum(Lam .* A)
//
// Per warp: 16 i-rows.  Per chunk (16 j): S = Xi@Xj^T via 6 HMMA (hi/lo bf16
// split, fp32-grade d2) -> exp epilogue in registers (diag forced to 1.0) ->
// D-fragment pair repacks directly into A-fragment -> Wacc += P@V (6 HMMA,
// P and V hi/lo split).  No smem round-trip for P.

#define N 8192
#define D 16
#define JS 8                     // j-splits
#define JT 128                   // j-tile rows
#define TILES_PER_CTA (N / JS / JT)   // 8
#define CHUNKS_PER_TILE (JT / 16)     // 8

#define LOG2E 1.4426950408889634f
#define GAMMA1 (-0.5f * LOG2E)
#define GAMMA2 (-0.125f * LOG2E)

#define XROW 48                  // padded Xj smem row stride (bytes)
#define VROW 136                 // Vt smem row stride (bf16 elems) = 272B

__device__ float g_sq[N];
__device__ float g_A[N * D];
__device__ float g_diff[N * D];
__device__ float g_W[N * D];

// ---------------------------------------------------------------------------
__device__ __forceinline__ uint32_t bf16x2(float lo, float hi) {
    uint32_t r;
    asm("cvt.rn.bf16x2.f32 %0, %1, %2;" : "=r"(r) : "f"(hi), "f"(lo));  // low half = 2nd operand
    return r;
}
__device__ __forceinline__ float ex2a(float x) {
    float y;
    asm("ex2.approx.f32 %0, %1;" : "=f"(y) : "f"(x));
    return y;
}
__device__ __forceinline__ float lo_of(uint32_t p) {   // float(bf16 low half)
    return __uint_as_float(p << 16);
}
__device__ __forceinline__ float hi_of(uint32_t p) {   // float(bf16 high half)
    return __uint_as_float(p & 0xffff0000u);
}
// hi/lo split of a float pair into two bf16x2 regs
__device__ __forceinline__ void hilo2(float x, float y, uint32_t& h, uint32_t& l) {
    h = bf16x2(x, y);
    l = bf16x2(x - lo_of(h), y - hi_of(h));
}
// mma.sync m16n8k16 row.col f32.bf16.bf16.f32, D==C accumulate
__device__ __forceinline__ void mma16816(float* d, const uint32_t* a,
                                         uint32_t b0, uint32_t b1) {
    asm volatile("mma.sync.aligned.m16n8k16.row.col.f32.bf16.bf16.f32 "
                 "{%0,%1,%2,%3}, {%4,%5,%6,%7}, {%8,%9}, {%0,%1,%2,%3};"
                 : "+f"(d[0]), "+f"(d[1]), "+f"(d[2]), "+f"(d[3])
                 : "r"(a[0]), "r"(a[1]), "r"(a[2]), "r"(a[3]), "r"(b0), "r"(b1));
}

// ---------------------------------------------------------------------------
__global__ void __launch_bounds__(256) prep_kernel(const float* __restrict__ X,
                                                   float* __restrict__ out) {
    int i = blockIdx.x * 256 + threadIdx.x;
    if (i == 0) out[0] = 0.0f;
    const float4* xp = (const float4*)(X + (size_t)i * D);
    float s = 0.0f;
    float4 z = make_float4(0.f, 0.f, 0.f, 0.f);
    float4* ap = (float4*)(g_A + (size_t)i * D);
#pragma unroll
    for (int k = 0; k < 4; k++) {
        float4 v = xp[k];
        s += v.x * v.x + v.y * v.y + v.z * v.z + v.w * v.w;
        ap[k] = z;
    }
    g_sq[i] = s;
}

// ---------------------------------------------------------------------------
// rbf_mv: Wout += K_gamma(X) @ V over this CTA's (i-block, j-split)
// mode 0: V=Lam -> g_A ; mode 1: V=g_diff -> g_W   (selected DEVICE-side)
// 256 threads = 8 warps; warp w owns i rows blockIdx.x*128 + w*16 .. +15
// ---------------------------------------------------------------------------
__global__ void __launch_bounds__(256) rbf_mv_kernel(const float* __restrict__ X,
                                                     const float* __restrict__ Lam,
                                                     float gamma, int mode) {
    __shared__ __align__(16) unsigned char s_xh[JT * XROW];      // Xj hi bf16 [j][d]
    __shared__ __align__(16) unsigned char s_xl[JT * XROW];      // Xj lo
    __shared__ __nv_bfloat16 s_vth[D * VROW];                    // V^T hi [d][j]
    __shared__ __nv_bfloat16 s_vtl[D * VROW];                    // V^T lo
    __shared__ float s_cs[JT];                                   // gamma*sq_j

    const float* V = mode ? g_diff : Lam;   // device-side: valid global addresses
    float* Wout    = mode ? g_W    : g_A;

    const int tid  = threadIdx.x;
    const int lane = tid & 31;
    const int w    = tid >> 5;
    const int g    = lane >> 2;       // group id (row)
    const int tg   = lane & 3;        // thread in group

    const int i0   = blockIdx.x * 128 + w * 16;
    const int row0 = i0 + g;
    const int row1 = i0 + g + 8;

    // --- A fragments for Xi (hi & lo), fixed for whole kernel ---
    uint32_t Ah[4], Al[4];
    {
        const float* r0 = X + (size_t)row0 * D;
        const float* r1 = X + (size_t)row1 * D;
        float2 p0 = *(const float2*)(r0 + 2 * tg);
        float2 p1 = *(const float2*)(r1 + 2 * tg);
        float2 p2 = *(const float2*)(r0 + 2 * tg + 8);
        float2 p3 = *(const float2*)(r1 + 2 * tg + 8);
        hilo2(p0.x, p0.y, Ah[0], Al[0]);
        hilo2(p1.x, p1.y, Ah[1], Al[1]);
        hilo2(p2.x, p2.y, Ah[2], Al[2]);
        hilo2(p3.x, p3.y, Ah[3], Al[3]);
    }
    const float base0 = gamma * g_sq[row0];
    const float base1 = gamma * g_sq[row1];

    float Wacc[8];
#pragma unroll
    for (int k = 0; k < 8; k++) Wacc[k] = 0.0f;

#pragma unroll 1
    for (int t = 0; t < TILES_PER_CTA; t++) {
        const int jt = blockIdx.y * (N / JS) + t * JT;
        __syncthreads();   // everyone done reading previous tile

        // ---- fill shared: Xj hi/lo [j][d], V^T hi/lo [d][j], cs ----
        {
            const int r  = tid >> 1;              // 0..127
            const int dh = (tid & 1) * 8;         // 0 or 8
            const float4* xr = (const float4*)(X + (size_t)(jt + r) * D + dh);
            float4 a = xr[0], b = xr[1];
            uint32_t h0, l0, h1, l1, h2, l2, h3, l3;
            hilo2(a.x, a.y, h0, l0);
            hilo2(a.z, a.w, h1, l1);
            hilo2(b.x, b.y, h2, l2);
            hilo2(b.z, b.w, h3, l3);
            *(uint4*)(s_xh + r * XROW + dh * 2) = make_uint4(h0, h1, h2, h3);
            *(uint4*)(s_xl + r * XROW + dh * 2) = make_uint4(l0, l1, l2, l3);

            const float4* vr = (const float4*)(V + (size_t)(jt + r) * D + dh);
            float4 va = vr[0], vb = vr[1];
            float vv[8] = {va.x, va.y, va.z, va.w, vb.x, vb.y, vb.z, vb.w};
#pragma unroll
            for (int d = 0; d < 8; d++) {
                __nv_bfloat16 hb = __float2bfloat16(vv[d]);
                s_vth[(dh + d) * VROW + r] = hb;
                s_vtl[(dh + d) * VROW + r] =
                    __float2bfloat16(vv[d] - __bfloat162float(hb));
            }
            if (tid < JT) s_cs[tid] = gamma * g_sq[jt + tid];
        }
        __syncthreads();

#pragma unroll 1
        for (int c = 0; c < CHUNKS_PER_TILE; c++) {
            const int jc    = c * 16;
            const int jglob = jt + jc;

            // ---- MMA1: S = Xi @ Xj^T (hi/lo split, 6 mma) ----
            float S[8];
#pragma unroll
            for (int k = 0; k < 8; k++) S[k] = 0.0f;
#pragma unroll
            for (int half = 0; half < 2; half++) {
                const int jr = jc + half * 8 + g;
                uint32_t bh0 = *(const uint32_t*)(s_xh + jr * XROW + 4 * tg);
                uint32_t bh1 = *(const uint32_t*)(s_xh + jr * XROW + 4 * tg + 16);
                uint32_t bl0 = *(const uint32_t*)(s_xl + jr * XROW + 4 * tg);
                uint32_t bl1 = *(const uint32_t*)(s_xl + jr * XROW + 4 * tg + 16);
                mma16816(S + half * 4, Ah, bh0, bh1);
                mma16816(S + half * 4, Al, bh0, bh1);
                mma16816(S + half * 4, Ah, bl0, bl1);
            }

            // ---- epilogue: p = exp2(gamma*d2), clamp, diag = 1 ----
            const float2 csA = *(const float2*)&s_cs[jc + 2 * tg];
            const float2 csB = *(const float2*)&s_cs[jc + 8 + 2 * tg];
            const float m2g = -2.0f * gamma;
            float p[8];
            p[0] = ex2a(fminf(fmaf(m2g, S[0], base0 + csA.x), 0.0f));
            p[1] = ex2a(fminf(fmaf(m2g, S[1], base0 + csA.y), 0.0f));
            p[2] = ex2a(fminf(fmaf(m2g, S[2], base1 + csA.x), 0.0f));
            p[3] = ex2a(fminf(fmaf(m2g, S[3], base1 + csA.y), 0.0f));
            p[4] = ex2a(fminf(fmaf(m2g, S[4], base0 + csB.x), 0.0f));
            p[5] = ex2a(fminf(fmaf(m2g, S[5], base0 + csB.y), 0.0f));
            p[6] = ex2a(fminf(fmaf(m2g, S[6], base1 + csB.x), 0.0f));
            p[7] = ex2a(fminf(fmaf(m2g, S[7], base1 + csB.y), 0.0f));
            if (i0 == jglob) {   // uniform per warp-chunk; exact diagonal k = 1
                const int jA = jglob + 2 * tg, jB = jglob + 8 + 2 * tg;
                if (row0 == jA)     p[0] = 1.0f;
                if (row0 == jA + 1) p[1] = 1.0f;
                if (row1 == jA)     p[2] = 1.0f;
                if (row1 == jA + 1) p[3] = 1.0f;
                if (row0 == jB)     p[4] = 1.0f;
                if (row0 == jB + 1) p[5] = 1.0f;
                if (row1 == jB)     p[6] = 1.0f;
                if (row1 == jB + 1) p[7] = 1.0f;
            }
            // D-fragment pair -> A-fragment repack (register-exact), hi/lo split
            uint32_t Ph[4], Pl[4];
            hilo2(p[0], p[1], Ph[0], Pl[0]);
            hilo2(p[2], p[3], Ph[1], Pl[1]);
            hilo2(p[4], p[5], Ph[2], Pl[2]);
            hilo2(p[6], p[7], Ph[3], Pl[3]);

            // ---- MMA2: Wacc += P @ V  (hi/lo split, 6 mma) ----
#pragma unroll
            for (int nh = 0; nh < 2; nh++) {
                const int dr = nh * 8 + g;
                uint32_t vh0 = *(const uint32_t*)&s_vth[dr * VROW + jc + 2 * tg];
                uint32_t vh1 = *(const uint32_t*)&s_vth[dr * VROW + jc + 2 * tg + 8];
                uint32_t vl0 = *(const uint32_t*)&s_vtl[dr * VROW + jc + 2 * tg];
                uint32_t vl1 = *(const uint32_t*)&s_vtl[dr * VROW + jc + 2 * tg + 8];
                mma16816(Wacc + nh * 4, Ph, vh0, vh1);
                mma16816(Wacc + nh * 4, Pl, vh0, vh1);
                mma16816(Wacc + nh * 4, Ph, vl0, vl1);
            }
        }
    }

    // ---- writeback: D-frag (row g/g+8, col 2tg..) per n-half ----
#pragma unroll
    for (int nh = 0; nh < 2; nh++) {
        const int col = nh * 8 + 2 * tg;
        atomicAdd(&Wout[(size_t)row0 * D + col],     Wacc[nh * 4 + 0]);
        atomicAdd(&Wout[(size_t)row0 * D + col + 1], Wacc[nh * 4 + 1]);
        atomicAdd(&Wout[(size_t)row1 * D + col],     Wacc[nh * 4 + 2]);
        atomicAdd(&Wout[(size_t)row1 * D + col + 1], Wacc[nh * 4 + 3]);
    }
}

// ---------------------------------------------------------------------------
__global__ void __launch_bounds__(256) mid_kernel(const float* __restrict__ Y) {
    int k = blockIdx.x * 256 + threadIdx.x;
    g_diff[k] = g_A[k] - Y[k];
    g_W[k] = 0.0f;
}

__global__ void __launch_bounds__(256) final_kernel(const float* __restrict__ Lam,
                                                    float* __restrict__ out) {
    __shared__ float s_red[8];
    float s = 0.0f;
    for (int k = blockIdx.x * 256 + threadIdx.x; k < N * D; k += gridDim.x * 256)
        s += g_diff[k] * g_W[k] + 0.01f * Lam[k] * g_A[k];
#pragma unroll
    for (int o = 16; o > 0; o >>= 1) s += __shfl_xor_sync(0xffffffffu, s, o);
    const int lane = threadIdx.x & 31, wd = threadIdx.x >> 5;
    if (lane == 0) s_red[wd] = s;
    __syncthreads();
    if (threadIdx.x == 0) {
        float t = 0.0f;
#pragma unroll
        for (int q = 0; q < 8; q++) t += s_red[q];
        atomicAdd(out, t);
    }
}

// ---------------------------------------------------------------------------
extern "C" void kernel_launch(void* const* d_in, const int* in_sizes, int n_in,
                              void* d_out, int out_size) {
    const float* X   = (const float*)d_in[0];
    const float* Y   = (const float*)d_in[1];
    const float* Lam = (const float*)d_in[2];
    float* out = (float*)d_out;

    prep_kernel<<<N / 256, 256>>>(X, out);

    dim3 grid(N / 128, JS);
    rbf_mv_kernel<<<grid, 256>>>(X, Lam, GAMMA1, 0);   // A = Kfit @ Lam
    mid_kernel<<<N * D / 256, 256>>>(Y);               // diff = A - Y, W = 0
    rbf_mv_kernel<<<grid, 256>>>(X, Lam, GAMMA2, 1);   // W = Kmmd @ diff
    final_kernel<<<128, 256>>>(Lam, out);
}